// round 2
// baseline (speedup 1.0000x reference)
#include <cuda_runtime.h>

// EuclideanCodebook: argmin_c ||x_m - e_c||^2 over C=8192 codes, D=256,
// M = B*N = 16384 rows. Outputs: quantize[M,D] (gathered codebook rows) and
// embed_ind[M] (as float), concatenated in d_out.
//
// Strategy: fp32 register-tiled GEMM (xe = X @ E^T) fused with running argmin.
// d2 replicated in reference order: fp32( fp32(x2 - 2*xe) + e2 ), ties -> lowest
// index via packed (float_bits<<32 | idx) u64 min (d2 > 0 so raw bits order OK).

#define DD 256
#define BM 128
#define BN 128
#define BK 8
#define CSPLIT 8
#define MAXM 16384
#define MAXC 8192

__device__ unsigned long long g_key[MAXM];
__device__ float g_x2[MAXM];
__device__ float g_e2[MAXC];

// ---------------------------------------------------------------------------
// Prep: warp-per-row squared-norm (coalesced float4 lane-strided loads,
// butterfly tree reduce), covering X rows then E rows. Also inits keys.
// ---------------------------------------------------------------------------
__global__ void ec_prep_kernel(const float* __restrict__ x,
                               const float* __restrict__ e,
                               int M, int C) {
    const int warp = (blockIdx.x * blockDim.x + threadIdx.x) >> 5;
    const int lane = threadIdx.x & 31;
    if (warp >= M + C) return;

    const float* row = (warp < M) ? (x + (size_t)warp * DD)
                                  : (e + (size_t)(warp - M) * DD);
    // 256 floats = 64 float4; 32 lanes * 2 float4 each, lane-strided
    const float4* p = (const float4*)row;
    float4 v0 = p[lane];
    float4 v1 = p[lane + 32];
    float s = v0.x * v0.x + v0.y * v0.y + v0.z * v0.z + v0.w * v0.w
            + v1.x * v1.x + v1.y * v1.y + v1.z * v1.z + v1.w * v1.w;
    #pragma unroll
    for (int off = 16; off > 0; off >>= 1)
        s += __shfl_xor_sync(0xFFFFFFFFu, s, off);

    if (lane == 0) {
        if (warp < M) {
            g_x2[warp] = s;
            g_key[warp] = 0xFFFFFFFFFFFFFFFFull;
        } else {
            g_e2[warp - M] = s;
        }
    }
}

// ---------------------------------------------------------------------------
// Fused GEMM + argmin. Block: 128 rows x (C/CSPLIT) codes in chunks of 128.
// 256 threads, 8x8 microtile, double-buffered smem, K loop over D=256.
// ---------------------------------------------------------------------------
__global__ __launch_bounds__(256, 2)
void ec_argmin_kernel(const float* __restrict__ X,
                      const float* __restrict__ E,
                      int M, int C) {
    __shared__ float Xs[2][BK][BM];
    __shared__ float Es[2][BK][BN];
    __shared__ float x2s[BM];
    __shared__ float e2s[BN];

    const int tid = threadIdx.x;
    const int tx = tid & 15;   // code group
    const int ty = tid >> 4;   // row group
    const int row0 = blockIdx.x * BM;
    const int cbase = blockIdx.y * (C / CSPLIT);

    if (tid < BM) x2s[tid] = g_x2[row0 + tid];

    // loader mapping: 256 threads * float4 = 1024 floats = 128 x 8 tile
    const int lm = tid >> 1;          // 0..127 (row / code within tile)
    const int lk = (tid & 1) * 4;     // 0 or 4 (k offset)
    const float* xg = X + (size_t)(row0 + lm) * DD + lk;

    unsigned long long best[8];
    #pragma unroll
    for (int i = 0; i < 8; i++) best[i] = 0xFFFFFFFFFFFFFFFFull;

    const int nchunks = (C / CSPLIT) / BN;
    for (int cc = 0; cc < nchunks; cc++) {
        const int c0 = cbase + cc * BN;
        __syncthreads();  // protect smem reuse from previous chunk
        if (tid < BN) e2s[tid] = g_e2[c0 + tid];
        const float* eg = E + (size_t)(c0 + lm) * DD + lk;

        // stage kt = 0
        {
            float4 vx = *(const float4*)xg;
            float4 ve = *(const float4*)eg;
            #pragma unroll
            for (int j = 0; j < 4; j++) {
                Xs[0][lk + j][lm] = ((const float*)&vx)[j];
                Es[0][lk + j][lm] = ((const float*)&ve)[j];
            }
        }
        __syncthreads();

        float acc[8][8];
        #pragma unroll
        for (int i = 0; i < 8; i++)
            #pragma unroll
            for (int j = 0; j < 8; j++) acc[i][j] = 0.0f;

        int cur = 0;
        for (int kt = 0; kt < DD / BK; kt++) {
            float4 nvx, nve;
            const bool more = (kt + 1) < (DD / BK);
            if (more) {
                nvx = *(const float4*)(xg + (kt + 1) * BK);
                nve = *(const float4*)(eg + (kt + 1) * BK);
            }
            #pragma unroll
            for (int k = 0; k < BK; k++) {
                float a[8], b[8];
                *(float4*)&a[0] = *(const float4*)&Xs[cur][k][ty * 8];
                *(float4*)&a[4] = *(const float4*)&Xs[cur][k][ty * 8 + 4];
                *(float4*)&b[0] = *(const float4*)&Es[cur][k][tx * 8];
                *(float4*)&b[4] = *(const float4*)&Es[cur][k][tx * 8 + 4];
                #pragma unroll
                for (int i = 0; i < 8; i++)
                    #pragma unroll
                    for (int j = 0; j < 8; j++)
                        acc[i][j] = fmaf(a[i], b[j], acc[i][j]);
            }
            if (more) {
                int nxt = cur ^ 1;
                #pragma unroll
                for (int j = 0; j < 4; j++) {
                    Xs[nxt][lk + j][lm] = ((const float*)&nvx)[j];
                    Es[nxt][lk + j][lm] = ((const float*)&nve)[j];
                }
                __syncthreads();
                cur = nxt;
            }
        }

        // d2 = (x2 - 2*xe) + e2 in reference rounding order; track min key
        #pragma unroll
        for (int i = 0; i < 8; i++) {
            float xx = x2s[ty * 8 + i];
            #pragma unroll
            for (int j = 0; j < 8; j++) {
                int c = c0 + tx * 8 + j;
                float val = __fadd_rn(__fsub_rn(xx, 2.0f * acc[i][j]),
                                      e2s[tx * 8 + j]);
                unsigned long long key =
                    ((unsigned long long)__float_as_uint(val) << 32) |
                    (unsigned int)c;
                best[i] = (key < best[i]) ? key : best[i];
            }
        }
    }

    // reduce over the 16 tx lanes (contiguous half-warp), then atomicMin
    #pragma unroll
    for (int i = 0; i < 8; i++) {
        unsigned long long k = best[i];
        #pragma unroll
        for (int off = 8; off > 0; off >>= 1) {
            unsigned long long o = __shfl_down_sync(0xFFFFFFFFu, k, off, 16);
            k = (o < k) ? o : k;
        }
        if (tx == 0) atomicMin(&g_key[row0 + ty * 8 + i], k);
    }
}

// ---------------------------------------------------------------------------
// Gather: quantize rows from codebook + write indices (as float).
// mode: bit0 = write quantize, bit1 = write indices after quantize region
// ---------------------------------------------------------------------------
__global__ void ec_gather_kernel(const float* __restrict__ E,
                                 float* __restrict__ out,
                                 int M, int mode) {
    int m = blockIdx.x;
    unsigned long long key = g_key[m];
    int c = (int)(unsigned int)(key & 0xFFFFFFFFull);
    int t = threadIdx.x;  // 64 threads
    if (mode & 1) {
        float4 v = *(const float4*)(E + (size_t)c * DD + t * 4);
        *(float4*)(out + (size_t)m * DD + t * 4) = v;
        if (t == 0 && (mode & 2)) out[(size_t)M * DD + m] = (float)c;
    } else {
        if (t == 0) out[m] = (float)c;
    }
}

// ---------------------------------------------------------------------------
extern "C" void kernel_launch(void* const* d_in, const int* in_sizes, int n_in,
                              void* d_out, int out_size) {
    const float* x = (const float*)d_in[0];   // [B,N,D] = [M, 256]
    const float* e = (const float*)d_in[1];   // [1,C,D] = [8192, 256]
    const int M = in_sizes[0] / DD;           // 16384
    const int C = in_sizes[1] / DD;           // 8192

    // warp per row: (M + C) warps, 256 threads = 8 warps per block
    const int nwarps = M + C;
    ec_prep_kernel<<<(nwarps + 7) / 8, 256>>>(x, e, M, C);

    dim3 grid(M / BM, CSPLIT);
    ec_argmin_kernel<<<grid, 256>>>(x, e, M, C);

    int mode;
    if (out_size >= M * DD + M)      mode = 3;  // quantize + indices
    else if (out_size >= M * DD)     mode = 1;  // quantize only
    else                             mode = 0;  // indices only
    ec_gather_kernel<<<M, 64>>>(e, (float*)d_out, M, mode);
}

// round 12
// speedup vs baseline: 1.2997x; 1.2997x over previous
#include <cuda_runtime.h>
#include <cstdint>

// EuclideanCodebook via 3xTF32 mma.sync (m16n8k8) GEMM + fused argmin.
// Toolchain constraint: harness lowers PTX at target sm_103 (no 'a' suffix),
// so tcgen05/TMEM are unavailable; mma.sync tf32 is baseline sm_80+ and maps
// to the legacy tensor-core path on GB300.
//
// Math: x = xh + xl, e = eh + el (tf32 splits, rna). xe ~= xh*eh + xh*el + xl*eh
// (residual ~1e-9 << min top-2 argmin gap -> exact argmin).
// d2 replicated in reference order: fp32( fp32(x2 - 2*xe) + e2 ); ties -> lowest
// index via packed (f32bits<<32 | idx) u64 atomicMin (d2 > 0 so bit order OK).

#define DD 256
#define KS 512              // stored K per matrix: [hi(0..255) | lo(256..511)]
#define BM 128
#define BN 256
#define KC 32               // k per pipeline chunk
#define KCP 36              // padded smem row stride in floats (bank-conflict-free)
#define NCHUNK 24           // 3 segments x 8 chunks (effective K = 768)
#define MAXM 16384
#define MAXC 8192

#define A_BYTES (BM * KCP * 4)            // 18432
#define B_BYTES (BN * KCP * 4)            // 36864
#define STAGE_BYTES (A_BYTES + B_BYTES)   // 55296
#define SMEM_E2 (3 * STAGE_BYTES)         // 165888
#define SMEM_TOTAL (SMEM_E2 + BN * 4)     // 166912

__device__ unsigned long long g_key[MAXM];
__device__ float g_x2[MAXM];
__device__ float g_e2[MAXC];
__device__ float g_xs[(size_t)MAXM * KS];
__device__ float g_es[(size_t)MAXC * KS];

// ---------------------------------------------------------------------------
#define CP_ASYNC16(dst, src) \
    asm volatile("cp.async.cg.shared.global [%0], [%1], 16;" :: "r"(dst), "l"(src))
#define CP_COMMIT() asm volatile("cp.async.commit_group;" ::: "memory")
#define CP_WAIT(n)  asm volatile("cp.async.wait_group %0;" :: "n"(n) : "memory")

__device__ __forceinline__ uint32_t smem_u32(const void* p) {
    uint32_t a;
    asm("{ .reg .u64 t; cvta.to.shared.u64 t, %1; cvt.u32.u64 %0, t; }"
        : "=r"(a) : "l"(p));
    return a;
}

// mma.sync m16n8k8 tf32: D(16x8 f32) += A(16x8 tf32, row) * B(8x8 tf32, col)
__device__ __forceinline__ void mma_tf32(float* c, const uint32_t* a,
                                         const uint32_t* b) {
    asm volatile(
        "mma.sync.aligned.m16n8k8.row.col.f32.tf32.tf32.f32 "
        "{%0,%1,%2,%3}, {%4,%5,%6,%7}, {%8,%9}, {%0,%1,%2,%3};"
        : "+f"(c[0]), "+f"(c[1]), "+f"(c[2]), "+f"(c[3])
        : "r"(a[0]), "r"(a[1]), "r"(a[2]), "r"(a[3]), "r"(b[0]), "r"(b[1]));
}

// ---------------------------------------------------------------------------
// Prep 1: row norms (warp per row, tree reduce) + key init. (rel_err 0 in R2)
// ---------------------------------------------------------------------------
__global__ void ec_prep_norms(const float* __restrict__ x,
                              const float* __restrict__ e, int M, int C) {
    const int warp = (blockIdx.x * blockDim.x + threadIdx.x) >> 5;
    const int lane = threadIdx.x & 31;
    if (warp >= M + C) return;
    const float* row = (warp < M) ? (x + (size_t)warp * DD)
                                  : (e + (size_t)(warp - M) * DD);
    const float4* p = (const float4*)row;
    float4 v0 = p[lane];
    float4 v1 = p[lane + 32];
    float s = v0.x * v0.x + v0.y * v0.y + v0.z * v0.z + v0.w * v0.w
            + v1.x * v1.x + v1.y * v1.y + v1.z * v1.z + v1.w * v1.w;
    #pragma unroll
    for (int off = 16; off > 0; off >>= 1)
        s += __shfl_xor_sync(0xFFFFFFFFu, s, off);
    if (lane == 0) {
        if (warp < M) { g_x2[warp] = s; g_key[warp] = 0xFFFFFFFFFFFFFFFFull; }
        else          { g_e2[warp - M] = s; }
    }
}

// ---------------------------------------------------------------------------
// Prep 2: tf32 hi/lo split into [hi | lo] K=512 operands.
// ---------------------------------------------------------------------------
__global__ void ec_prep_split(const float* __restrict__ x,
                              const float* __restrict__ e, int M, int C) {
    int i = blockIdx.x * blockDim.x + threadIdx.x;
    int total = (M + C) * DD;
    if (i >= total) return;
    float v, *dst;
    if (i < M * DD) {
        int m = i >> 8, d = i & 255;
        v = x[i];
        dst = g_xs + (size_t)m * KS + d;
    } else {
        int j = i - M * DD;
        int c = j >> 8, d = j & 255;
        v = e[j];
        dst = g_es + (size_t)c * KS + d;
    }
    float hi, lo, lor;
    asm("cvt.rna.tf32.f32 %0, %1;" : "=f"(hi) : "f"(v));
    lo = __fsub_rn(v, hi);
    asm("cvt.rna.tf32.f32 %0, %1;" : "=f"(lor) : "f"(lo));
    dst[0] = hi;
    dst[256] = lor;
}

// ---------------------------------------------------------------------------
// Main: 3xTF32 mma.sync GEMM (BM=128 x BN=256, 24 K-chunks of 32 over
// 3 hi/lo segment pairs), 3-stage cp.async pipeline, fused argmin epilogue.
// 256 threads = 8 warps (2 M-groups x 4 N-groups), warp tile 64x64.
// ---------------------------------------------------------------------------
__global__ __launch_bounds__(256, 1)
void ec_mma_kernel(int M, int C) {
    extern __shared__ __align__(16) char smem[];
    const int tid = threadIdx.x;
    const int wid = tid >> 5;
    const int lane = tid & 31;
    const int g = lane >> 2;           // 0..7
    const int q = lane & 3;            // 0..3
    const int warpM = (wid >> 2) * 64; // 0 or 64
    const int warpN = (wid & 3) * 64;  // 0..192
    const int row0 = blockIdx.x * BM;
    const int c0 = blockIdx.y * BN;

    float* e2s = (float*)(smem + SMEM_E2);
    #pragma unroll
    for (int j = 0; j < BN / 256; j++) e2s[j * 256 + tid] = g_e2[c0 + j * 256 + tid];

    // segment k-offsets: (xh,eh), (xh,el), (xl,eh)
    const int SA[3] = {0, 0, 256};
    const int SB[3] = {0, 256, 0};

    // issue one K-chunk (idx: 0..23) into a pipeline slot
    auto cp_chunk = [&](int slot, int idx) {
        const int seg = idx >> 3;
        const int kc = (idx & 7) * KC;
        const int colA = SA[seg] + kc;
        const int colB = SB[seg] + kc;
        uint32_t abase = smem_u32(smem) + slot * STAGE_BYTES;
        uint32_t bbase = abase + A_BYTES;
        #pragma unroll
        for (int t = 0; t < 12; t++) {
            int idx2 = tid + t * 256;                 // 0..3071
            if (idx2 < 1024) {
                int r = idx2 >> 3, ch = idx2 & 7;
                const float* src = g_xs + (size_t)(row0 + r) * KS + colA + ch * 4;
                CP_ASYNC16(abase + (uint32_t)(r * (KCP * 4) + ch * 16), src);
            } else {
                int j = idx2 - 1024;
                int r = j >> 3, ch = j & 7;
                const float* src = g_es + (size_t)(c0 + r) * KS + colB + ch * 4;
                CP_ASYNC16(bbase + (uint32_t)(r * (KCP * 4) + ch * 16), src);
            }
        }
        CP_COMMIT();
    };

    float acc[4][8][4];
    #pragma unroll
    for (int mt = 0; mt < 4; mt++)
        #pragma unroll
        for (int nt = 0; nt < 8; nt++)
            #pragma unroll
            for (int c = 0; c < 4; c++) acc[mt][nt][c] = 0.0f;

    // prologue: chunks 0,1 -> slots 0,1
    cp_chunk(0, 0);
    cp_chunk(1, 1);

    for (int i = 0; i < NCHUNK; i++) {
        const int slot = i % 3;
        if (i + 2 < NCHUNK) {
            CP_WAIT(1);            // chunk i resident
            __syncthreads();       // all warps done with slot (i-1)%3 == (i+2)%3
            cp_chunk((i + 2) % 3, i + 2);
        } else if (i + 1 < NCHUNK) {
            CP_WAIT(1);
            __syncthreads();
        } else {
            CP_WAIT(0);
            __syncthreads();
        }

        const uint32_t* As = (const uint32_t*)(smem + slot * STAGE_BYTES);
        const uint32_t* Bs = (const uint32_t*)(smem + slot * STAGE_BYTES + A_BYTES);

        #pragma unroll
        for (int kk = 0; kk < KC / 8; kk++) {
            uint32_t a[4][4], b[8][2];
            #pragma unroll
            for (int mt = 0; mt < 4; mt++) {
                int base = (warpM + 16 * mt + g) * KCP + kk * 8 + q;
                a[mt][0] = As[base];
                a[mt][1] = As[base + 8 * KCP];
                a[mt][2] = As[base + 4];
                a[mt][3] = As[base + 8 * KCP + 4];
            }
            #pragma unroll
            for (int nt = 0; nt < 8; nt++) {
                int nb = (warpN + 8 * nt + g) * KCP + kk * 8 + q;
                b[nt][0] = Bs[nb];
                b[nt][1] = Bs[nb + 4];
            }
            #pragma unroll
            for (int mt = 0; mt < 4; mt++)
                #pragma unroll
                for (int nt = 0; nt < 8; nt++)
                    mma_tf32(acc[mt][nt], a[mt], b[nt]);
        }
    }

    // epilogue: d2 = (x2 - 2*xe) + e2 in reference rounding order; argmin keys.
    // D layout per tile: c0/c1 -> row g, cols 2q/2q+1; c2/c3 -> row g+8.
    #pragma unroll
    for (int mt = 0; mt < 4; mt++) {
        const int rl = row0 + warpM + 16 * mt + g;
        const float x2l = g_x2[rl];
        const float x2h = g_x2[rl + 8];
        unsigned long long bl = 0xFFFFFFFFFFFFFFFFull;
        unsigned long long bh = 0xFFFFFFFFFFFFFFFFull;
        #pragma unroll
        for (int nt = 0; nt < 8; nt++) {
            #pragma unroll
            for (int c = 0; c < 4; c++) {
                const int col = warpN + 8 * nt + 2 * q + (c & 1);
                const float e2v = e2s[col];
                const float x2v = (c < 2) ? x2l : x2h;
                float val = __fadd_rn(__fsub_rn(x2v, 2.0f * acc[mt][nt][c]), e2v);
                unsigned long long key =
                    ((unsigned long long)__float_as_uint(val) << 32) |
                    (unsigned int)(c0 + col);
                if (c < 2) bl = (key < bl) ? key : bl;
                else       bh = (key < bh) ? key : bh;
            }
        }
        #pragma unroll
        for (int off = 1; off <= 2; off <<= 1) {
            unsigned long long o;
            o = __shfl_xor_sync(0xFFFFFFFFu, bl, off);
            bl = (o < bl) ? o : bl;
            o = __shfl_xor_sync(0xFFFFFFFFu, bh, off);
            bh = (o < bh) ? o : bh;
        }
        if (q == 0) {
            atomicMin(&g_key[rl], bl);
            atomicMin(&g_key[rl + 8], bh);
        }
    }
}

// ---------------------------------------------------------------------------
// Gather: quantize rows + indices (as float).
// ---------------------------------------------------------------------------
__global__ void ec_gather_kernel(const float* __restrict__ E,
                                 float* __restrict__ out, int M, int mode) {
    int m = blockIdx.x;
    unsigned long long key = g_key[m];
    int c = (int)(unsigned int)(key & 0xFFFFFFFFull);
    int t = threadIdx.x;  // 64 threads
    if (mode & 1) {
        float4 v = *(const float4*)(E + (size_t)c * DD + t * 4);
        *(float4*)(out + (size_t)m * DD + t * 4) = v;
        if (t == 0 && (mode & 2)) out[(size_t)M * DD + m] = (float)c;
    } else {
        if (t == 0) out[m] = (float)c;
    }
}

// ---------------------------------------------------------------------------
extern "C" void kernel_launch(void* const* d_in, const int* in_sizes, int n_in,
                              void* d_out, int out_size) {
    const float* x = (const float*)d_in[0];   // [M, 256]
    const float* e = (const float*)d_in[1];   // [8192, 256]
    const int M = in_sizes[0] / DD;
    const int C = in_sizes[1] / DD;

    // idempotent, not a stream op: safe to call every time (no static guards)
    cudaFuncSetAttribute(ec_mma_kernel,
                         cudaFuncAttributeMaxDynamicSharedMemorySize, SMEM_TOTAL);

    const int nwarps = M + C;
    ec_prep_norms<<<(nwarps + 7) / 8, 256>>>(x, e, M, C);
    ec_prep_split<<<((M + C) * DD + 255) / 256, 256>>>(x, e, M, C);

    dim3 grid(M / BM, C / BN);
    ec_mma_kernel<<<grid, 256, SMEM_TOTAL>>>(M, C);

    int mode;
    if (out_size >= M * DD + M)  mode = 3;
    else if (out_size >= M * DD) mode = 1;
    else                         mode = 0;
    ec_gather_kernel<<<M, 64>>>(e, (float*)d_out, M, mode);
}